// round 3
// baseline (speedup 1.0000x reference)
#include <cuda_runtime.h>
#include <math.h>

// Problem constants
#define D_DIM   1024
#define S_LEN   4096
#define B_SZ    2
#define A_DIM   64
#define DI_DIM  4096
#define TOPK    32
#define NROWS   (B_SZ * S_LEN)                 // 8192
#define ROWELEMS ((long)NROWS * D_DIM)         // 8,388,608

#define NEG_INF (-3.402823466e38f)

// ---------------------------------------------------------------------------
// Scratch: single static device array, offsets below (in floats).
// Layout (floats):
//   11 buffers of NROWS*D (8,388,608 each), then Q/K (NROWS*64 each),
//   scores (B*S*S = 33,554,432), Kc (NROWS*DI = 33,554,432).
// ---------------------------------------------------------------------------
#define BUF  8388608L
static const long O_H1    = 0L * BUF;   // h1 (also reused as h2)
static const long O_XV    = 1L * BUF;   // v-mixed input (reused as xk2)
static const long O_XR    = 2L * BUF;   // r-mixed input (reused as xr2)
static const long O_VTM   = 3L * BUF;   // tm value out (reused as tm out-proj result)
static const long O_RTM   = 4L * BUF;   // tm recept out
static const long O_VV    = 5L * BUF;   // sa V
static const long O_ATTN  = 6L * BUF;   // attn@V   (reused as rkv)
static const long O_ATTNO = 7L * BUF;   // attn out-proj
static const long O_X2    = 8L * BUF;   // x after time-mix residual
static const long O_R2    = 9L * BUF;   // cm recept out
static const long O_KV    = 10L * BUF;  // cm value out
static const long O_Q     = 11L * BUF;                 // 8192*64
static const long O_KK    = O_Q + (long)NROWS * A_DIM; // 8192*64
static const long O_SC    = O_KK + (long)NROWS * A_DIM;            // 33,554,432
static const long O_KC    = O_SC + (long)B_SZ * S_LEN * S_LEN;     // 33,554,432
static const long SCRATCH_FLOATS = O_KC + (long)NROWS * DI_DIM;    // 160,432,128

__device__ __align__(16) float g_scratch[160432128];

// ---------------------------------------------------------------------------
// RMSNorm: out = w * x / (||x||/sqrt(D) + 1e-8), one block per row of 1024.
// ---------------------------------------------------------------------------
__global__ void __launch_bounds__(256) rmsnorm_kernel(
    const float* __restrict__ x, const float* __restrict__ w,
    float* __restrict__ out)
{
    long row = blockIdx.x;
    const float* xr = x + row * D_DIM;
    int tid = threadIdx.x;

    float s = 0.f;
#pragma unroll
    for (int d = 0; d < 4; d++) {
        float v = xr[tid + d * 256];
        s += v * v;
    }
#pragma unroll
    for (int o = 16; o > 0; o >>= 1) s += __shfl_xor_sync(0xffffffffu, s, o);

    __shared__ float red[8];
    __shared__ float s_inv;
    if ((tid & 31) == 0) red[tid >> 5] = s;
    __syncthreads();
    if (tid == 0) {
        float t = 0.f;
#pragma unroll
        for (int i = 0; i < 8; i++) t += red[i];
        s_inv = 1.0f / (sqrtf(t / (float)D_DIM) + 1e-8f);
    }
    __syncthreads();
    float inv = s_inv;
#pragma unroll
    for (int d = 0; d < 4; d++) {
        int c = tid + d * 256;
        out[row * D_DIM + c] = w[c] * xr[c] * inv;
    }
}

// ---------------------------------------------------------------------------
// Token-shift mixing: two outputs at once.
// oA[t] = h[t]*mA + h[t-1]*(1-mA)   (t-1 within batch; t==0 uses itself)
// ---------------------------------------------------------------------------
__global__ void __launch_bounds__(256) mix2_kernel(
    const float* __restrict__ h,
    const float* __restrict__ mA, const float* __restrict__ mB,
    float* __restrict__ oA, float* __restrict__ oB)
{
    long row = blockIdx.x;
    long t = row & (S_LEN - 1);
    long prev = (t == 0) ? row : row - 1;
    int tid = threadIdx.x;
#pragma unroll
    for (int d = 0; d < 4; d++) {
        int c = tid + d * 256;
        float cur = h[row * D_DIM + c];
        float pv  = h[prev * D_DIM + c];
        float a = mA[c], b = mB[c];
        oA[row * D_DIM + c] = cur * a + pv * (1.f - a);
        oB[row * D_DIM + c] = cur * b + pv * (1.f - b);
    }
}

// ---------------------------------------------------------------------------
// SGEMM (NT): C[m,n] = alpha * sum_k A[m,k]*B[n,k] (+ bias[n]) (epi: relu^2)
// BM=BN=128, BK=16, 256 threads, 8x8 microtile. M%128==0, K%16==0 required;
// N handled with guards (needed for N=64).
// Batched via blockIdx.z with element strides sA/sB/sC.
// ---------------------------------------------------------------------------
template <int EPI>
__global__ void __launch_bounds__(256) gemm_nt(
    const float* __restrict__ A, const float* __restrict__ B,
    const float* __restrict__ bias, float* __restrict__ C,
    int M, int N, int K, float alpha,
    long sA, long sB, long sC)
{
    A += (long)blockIdx.z * sA;
    B += (long)blockIdx.z * sB;
    C += (long)blockIdx.z * sC;

    __shared__ float As[16][132];
    __shared__ float Bs[16][132];

    int bm = blockIdx.y * 128;
    int bn = blockIdx.x * 128;
    int tid = threadIdx.x;
    int tr = tid >> 4;        // 0..15
    int tc = tid & 15;        // 0..15

    float acc[8][8];
#pragma unroll
    for (int i = 0; i < 8; i++)
#pragma unroll
        for (int j = 0; j < 8; j++) acc[i][j] = 0.f;

    int lr = tid >> 2;          // 0..63
    int lc = (tid & 3) * 4;     // 0,4,8,12

    for (int k0 = 0; k0 < K; k0 += 16) {
#pragma unroll
        for (int half = 0; half < 2; half++) {
            int row = lr + half * 64;
            float4 a4 = *(const float4*)(A + (long)(bm + row) * K + k0 + lc);
            As[lc + 0][row] = a4.x;
            As[lc + 1][row] = a4.y;
            As[lc + 2][row] = a4.z;
            As[lc + 3][row] = a4.w;
            float4 b4 = make_float4(0.f, 0.f, 0.f, 0.f);
            if (bn + row < N)
                b4 = *(const float4*)(B + (long)(bn + row) * K + k0 + lc);
            Bs[lc + 0][row] = b4.x;
            Bs[lc + 1][row] = b4.y;
            Bs[lc + 2][row] = b4.z;
            Bs[lc + 3][row] = b4.w;
        }
        __syncthreads();
#pragma unroll
        for (int kk = 0; kk < 16; kk++) {
            float a[8], b[8];
            *(float4*)&a[0] = *(const float4*)&As[kk][tr * 8];
            *(float4*)&a[4] = *(const float4*)&As[kk][tr * 8 + 4];
            *(float4*)&b[0] = *(const float4*)&Bs[kk][tc * 8];
            *(float4*)&b[4] = *(const float4*)&Bs[kk][tc * 8 + 4];
#pragma unroll
            for (int i = 0; i < 8; i++)
#pragma unroll
                for (int j = 0; j < 8; j++)
                    acc[i][j] += a[i] * b[j];
        }
        __syncthreads();
    }

#pragma unroll
    for (int i = 0; i < 8; i++) {
        long crow = (long)(bm + tr * 8 + i) * N;
#pragma unroll
        for (int j = 0; j < 8; j++) {
            int col = bn + tc * 8 + j;
            if (col < N) {
                float v = acc[i][j] * alpha;
                if (bias) v += bias[col];
                if (EPI == 1) { v = fmaxf(v, 0.f); v = v * v; }
                C[crow + col] = v;
            }
        }
    }
}

// ---------------------------------------------------------------------------
// Sparse attention: per query row, top-32 of 4096 scores, softmax, attn@V.
// One block (256 threads) per query row.
// ---------------------------------------------------------------------------
__global__ void __launch_bounds__(256) sparse_attn_kernel(
    const float* __restrict__ scores, const float* __restrict__ V,
    float* __restrict__ out)
{
    __shared__ float sc[S_LEN];
    __shared__ float selV[TOPK];
    __shared__ int   selI[TOPK];
    __shared__ float rv[8];
    __shared__ int   ri[8];
    __shared__ float wsel[TOPK];

    long row = blockIdx.x;         // 0..8191  (= b*S + q)
    long b = row >> 12;            // row / 4096
    int tid = threadIdx.x;

    const float* srow = scores + row * S_LEN;
    for (int i = tid; i < S_LEN; i += 256) sc[i] = srow[i];
    __syncthreads();

    for (int it = 0; it < TOPK; it++) {
        float bv = NEG_INF;
        int bi = 0x7fffffff;
        for (int i = tid; i < S_LEN; i += 256) {
            float v = sc[i];
            if (v > bv || (v == bv && i < bi)) { bv = v; bi = i; }
        }
#pragma unroll
        for (int o = 16; o > 0; o >>= 1) {
            float ov = __shfl_down_sync(0xffffffffu, bv, o);
            int   oi = __shfl_down_sync(0xffffffffu, bi, o);
            if (ov > bv || (ov == bv && oi < bi)) { bv = ov; bi = oi; }
        }
        if ((tid & 31) == 0) { rv[tid >> 5] = bv; ri[tid >> 5] = bi; }
        __syncthreads();
        if (tid == 0) {
            float fv = rv[0]; int fi = ri[0];
#pragma unroll
            for (int w = 1; w < 8; w++) {
                if (rv[w] > fv || (rv[w] == fv && ri[w] < fi)) { fv = rv[w]; fi = ri[w]; }
            }
            selV[it] = fv; selI[it] = fi;
            sc[fi] = NEG_INF;
        }
        __syncthreads();
    }

    // softmax over the 32 selected (selV[0] is the global max)
    if (tid < TOPK) {
        float m = selV[0];
        float e = expf(selV[tid] - m);
        float s = e;
#pragma unroll
        for (int o = 16; o > 0; o >>= 1) s += __shfl_xor_sync(0xffffffffu, s, o);
        wsel[tid] = e / s;
    }
    __syncthreads();

    // out[row, :] = sum_j wsel[j] * V[b, selI[j], :]
    float acc[4] = {0.f, 0.f, 0.f, 0.f};
    const float* Vb = V + b * (long)S_LEN * D_DIM;
#pragma unroll 1
    for (int j = 0; j < TOPK; j++) {
        float w = wsel[j];
        const float* vr = Vb + (long)selI[j] * D_DIM;
#pragma unroll
        for (int d = 0; d < 4; d++) acc[d] += w * vr[tid + d * 256];
    }
#pragma unroll
    for (int d = 0; d < 4; d++)
        out[row * D_DIM + tid + d * 256] = acc[d];
}

// ---------------------------------------------------------------------------
// Elementwise kernels
// ---------------------------------------------------------------------------
__device__ __forceinline__ float sigmoidf_(float x) { return 1.f / (1.f + expf(-x)); }

// out = sigmoid(r) * (a + v)
__global__ void ew_gate_add(const float* __restrict__ r, const float* __restrict__ a,
                            const float* __restrict__ v, float* __restrict__ out, long n)
{
    long i = (long)blockIdx.x * blockDim.x + threadIdx.x;
    if (i < n) out[i] = sigmoidf_(r[i]) * (a[i] + v[i]);
}

// out = a + b
__global__ void ew_add(const float* __restrict__ a, const float* __restrict__ b,
                       float* __restrict__ out, long n)
{
    long i = (long)blockIdx.x * blockDim.x + threadIdx.x;
    if (i < n) out[i] = a[i] + b[i];
}

// out = res + sigmoid(r) * kv
__global__ void ew_gate_res(const float* __restrict__ res, const float* __restrict__ r,
                            const float* __restrict__ kv, float* __restrict__ out, long n)
{
    long i = (long)blockIdx.x * blockDim.x + threadIdx.x;
    if (i < n) out[i] = res[i] + sigmoidf_(r[i]) * kv[i];
}

// ---------------------------------------------------------------------------
// Host launcher
// ---------------------------------------------------------------------------
static void launch_gemm(const float* A, const float* B, const float* bias, float* C,
                        int M, int N, int K, float alpha, int batch,
                        long sA, long sB, long sC, int epi)
{
    dim3 grid((N + 127) / 128, (M + 127) / 128, batch);
    if (epi == 0)
        gemm_nt<0><<<grid, 256>>>(A, B, bias, C, M, N, K, alpha, sA, sB, sC);
    else
        gemm_nt<1><<<grid, 256>>>(A, B, bias, C, M, N, K, alpha, sA, sB, sC);
}

extern "C" void kernel_launch(void* const* d_in, const int* in_sizes, int n_in,
                              void* d_out, int out_size)
{
    const float* x         = (const float*)d_in[0];
    const float* norm1_w   = (const float*)d_in[1];
    // d_in[2] tm_mix_k: dead (k unused in time_mix)
    const float* tm_mix_v  = (const float*)d_in[3];
    const float* tm_mix_r  = (const float*)d_in[4];
    // d_in[5] tm_key_w: dead
    const float* tm_value_w  = (const float*)d_in[6];
    const float* tm_recept_w = (const float*)d_in[7];
    const float* tm_out_w    = (const float*)d_in[8];
    const float* sa_q_w    = (const float*)d_in[9];
    const float* sa_q_b    = (const float*)d_in[10];
    const float* sa_k_w    = (const float*)d_in[11];
    const float* sa_k_b    = (const float*)d_in[12];
    const float* sa_v_w    = (const float*)d_in[13];
    const float* sa_v_b    = (const float*)d_in[14];
    const float* sa_o_w    = (const float*)d_in[15];
    const float* sa_o_b    = (const float*)d_in[16];
    const float* norm2_w   = (const float*)d_in[17];
    const float* cm_mix_k  = (const float*)d_in[18];
    const float* cm_mix_r  = (const float*)d_in[19];
    const float* cm_key_w    = (const float*)d_in[20];
    const float* cm_recept_w = (const float*)d_in[21];
    const float* cm_value_w  = (const float*)d_in[22];
    float* out = (float*)d_out;

    float* sp = nullptr;
    cudaGetSymbolAddress((void**)&sp, g_scratch);

    float* h1    = sp + O_H1;
    float* xv    = sp + O_XV;
    float* xr    = sp + O_XR;
    float* Vtm   = sp + O_VTM;
    float* Rtm   = sp + O_RTM;
    float* Vv    = sp + O_VV;
    float* attn  = sp + O_ATTN;
    float* attno = sp + O_ATTNO;
    float* x2    = sp + O_X2;
    float* R2    = sp + O_R2;
    float* KV    = sp + O_KV;
    float* Q     = sp + O_Q;
    float* Kk    = sp + O_KK;
    float* SCo   = sp + O_SC;
    float* Kc    = sp + O_KC;

    const long n = ROWELEMS;
    const int ewBlocks = (int)((n + 255) / 256);

    // --- time-mix branch ---
    rmsnorm_kernel<<<NROWS, 256>>>(x, norm1_w, h1);
    mix2_kernel<<<NROWS, 256>>>(h1, tm_mix_v, tm_mix_r, xv, xr);

    launch_gemm(xv, tm_value_w,  nullptr, Vtm, NROWS, D_DIM, D_DIM, 1.f, 1, 0, 0, 0, 0);
    launch_gemm(xr, tm_recept_w, nullptr, Rtm, NROWS, D_DIM, D_DIM, 1.f, 1, 0, 0, 0, 0);
    launch_gemm(h1, sa_q_w, sa_q_b, Q,  NROWS, A_DIM, D_DIM, 1.f, 1, 0, 0, 0, 0);
    launch_gemm(h1, sa_k_w, sa_k_b, Kk, NROWS, A_DIM, D_DIM, 1.f, 1, 0, 0, 0, 0);
    launch_gemm(h1, sa_v_w, sa_v_b, Vv, NROWS, D_DIM, D_DIM, 1.f, 1, 0, 0, 0, 0);

    // scores[b] = (Q[b] @ K[b]^T) / sqrt(A)   (batched over B)
    launch_gemm(Q, Kk, nullptr, SCo, S_LEN, S_LEN, A_DIM, 0.125f, B_SZ,
                (long)S_LEN * A_DIM, (long)S_LEN * A_DIM, (long)S_LEN * S_LEN, 0);

    sparse_attn_kernel<<<NROWS, 256>>>(SCo, Vv, attn);

    launch_gemm(attn, sa_o_w, sa_o_b, attno, NROWS, D_DIM, D_DIM, 1.f, 1, 0, 0, 0, 0);

    // rkv = sigmoid(Rtm) * (attno + Vtm)  -> reuse attn buffer
    ew_gate_add<<<ewBlocks, 256>>>(Rtm, attno, Vtm, attn, n);

    // tm = rkv @ tm_out_w^T -> reuse Vtm buffer; x2 = x + tm
    launch_gemm(attn, tm_out_w, nullptr, Vtm, NROWS, D_DIM, D_DIM, 1.f, 1, 0, 0, 0, 0);
    ew_add<<<ewBlocks, 256>>>(x, Vtm, x2, n);

    // --- channel-mix branch ---
    rmsnorm_kernel<<<NROWS, 256>>>(x2, norm2_w, h1);            // h2 -> h1
    mix2_kernel<<<NROWS, 256>>>(h1, cm_mix_k, cm_mix_r, xv, xr); // xk2 -> xv, xr2 -> xr

    // Kc = relu(xk2 @ cm_key_w^T)^2
    launch_gemm(xv, cm_key_w, nullptr, Kc, NROWS, DI_DIM, D_DIM, 1.f, 1, 0, 0, 0, 1);
    launch_gemm(xr, cm_recept_w, nullptr, R2, NROWS, D_DIM, D_DIM, 1.f, 1, 0, 0, 0, 0);
    launch_gemm(Kc, cm_value_w, nullptr, KV, NROWS, D_DIM, DI_DIM, 1.f, 1, 0, 0, 0, 0);

    // out = x2 + sigmoid(R2) * KV
    ew_gate_res<<<ewBlocks, 256>>>(x2, R2, KV, out, n);
}

// round 7
// speedup vs baseline: 1.1936x; 1.1936x over previous
#include <cuda_runtime.h>
#include <math.h>
#include <stdint.h>

// Problem constants
#define D_DIM   1024
#define S_LEN   4096
#define B_SZ    2
#define A_DIM   64
#define DI_DIM  4096
#define TOPK    32
#define NROWS   (B_SZ * S_LEN)                 // 8192
#define ROWELEMS ((long)NROWS * D_DIM)         // 8,388,608

#define NEG_INF (-3.402823466e38f)

// ---------------------------------------------------------------------------
// Scratch
// ---------------------------------------------------------------------------
#define BUF  8388608L
static const long O_H1    = 0L * BUF;
static const long O_XV    = 1L * BUF;
static const long O_XR    = 2L * BUF;
static const long O_VTM   = 3L * BUF;
static const long O_RTM   = 4L * BUF;
static const long O_VV    = 5L * BUF;
static const long O_ATTN  = 6L * BUF;
static const long O_ATTNO = 7L * BUF;
static const long O_X2    = 8L * BUF;
static const long O_R2    = 9L * BUF;
static const long O_KV    = 10L * BUF;
static const long O_Q     = 11L * BUF;
static const long O_KK    = O_Q + (long)NROWS * A_DIM;
static const long O_SC    = O_KK + (long)NROWS * A_DIM;
static const long O_KC    = O_SC + (long)B_SZ * S_LEN * S_LEN;

__device__ __align__(16) float g_scratch[160432128];

// ===========================================================================
// mma.sync 3xTF32 GEMM (NT): C[m,n]=alpha*sum_k A[m,k]*B[n,k] (+bias)(relu^2)
// BM=BN=128, BK=16 floats, 4-stage cp.async pipeline, 256 threads (8 warps),
// warp grid 2(m) x 4(n), warp tile 64x32, fragments m16n8k8 tf32.
// Split precision: a*b ~= ah*bh + ah*bl + al*bh  (al,bl = tf32 residuals).
// Requires M%128==0, N%128==0, K%16==0.
// ===========================================================================
#define BM   128
#define BN   128
#define BKF  16
#define NSTG 4
#define STG_A_BYTES (BM * BKF * 4)      // 8192
#define STG_BYTES   (2 * STG_A_BYTES)   // 16384 (A then B)
#define GEMM_DSMEM  (NSTG * STG_BYTES)  // 65536

__device__ __forceinline__ void cp16(uint32_t s, const void* g) {
    asm volatile("cp.async.cg.shared.global [%0], [%1], 16;" :: "r"(s), "l"(g));
}

__device__ __forceinline__ uint32_t smem_u32(const void* p) {
    uint32_t a;
    asm("{ .reg .u64 t; cvta.to.shared.u64 t, %1; cvt.u32.u64 %0, t; }"
        : "=r"(a) : "l"(p));
    return a;
}

// round-to-nearest tf32 conversion (result in low bits of b32)
__device__ __forceinline__ uint32_t f2tf32(float x) {
    uint32_t r;
    asm("cvt.rna.tf32.f32 %0, %1;" : "=r"(r) : "f"(x));
    return r;
}

// hi/lo split: x = tf32(hi) + tf32(lo) + O(2^-21 x)
__device__ __forceinline__ void split_tf32(uint32_t xbits, uint32_t& hi, uint32_t& lo) {
    float x = __uint_as_float(xbits);
    hi = f2tf32(x);
    lo = f2tf32(x - __uint_as_float(hi));
}

// swizzled element fetch: tile is [rows][16 floats] with 16B-granule XOR swizzle
__device__ __forceinline__ uint32_t lde(const uint32_t* t, int row, int k) {
    int g = k >> 2;
    return t[row * 16 + (((g ^ ((row >> 1) & 3)) << 2) | (k & 3))];
}

__device__ __forceinline__ void mma1688(float* c, const uint32_t* a, const uint32_t* b) {
    asm volatile(
        "mma.sync.aligned.m16n8k8.row.col.f32.tf32.tf32.f32 "
        "{%0,%1,%2,%3}, {%4,%5,%6,%7}, {%8,%9}, {%0,%1,%2,%3};"
        : "+f"(c[0]), "+f"(c[1]), "+f"(c[2]), "+f"(c[3])
        : "r"(a[0]), "r"(a[1]), "r"(a[2]), "r"(a[3]), "r"(b[0]), "r"(b[1]));
}

__device__ __forceinline__ void load_stage_mma(
    uint32_t sbase, int stage, const float* __restrict__ A,
    const float* __restrict__ B, int bm, int bn, int k0, int K, int tid)
{
    uint32_t sa = sbase + stage * STG_BYTES;
    uint32_t sb = sa + STG_A_BYTES;
    int row = tid >> 1;            // 0..127
    int g0 = (tid & 1) * 2;        // granule pair
#pragma unroll
    for (int j = 0; j < 2; j++) {
        int g = g0 + j;
        uint32_t so = (uint32_t)(row * 64 + ((g ^ ((row >> 1) & 3)) << 4));
        cp16(sa + so, A + (long)(bm + row) * K + k0 + g * 4);
        cp16(sb + so, B + (long)(bn + row) * K + k0 + g * 4);
    }
}

template<int RELU2>
__global__ void __launch_bounds__(256) gemm_mma(
    const float* __restrict__ A, const float* __restrict__ B,
    const float* __restrict__ bias, float* __restrict__ C,
    int M, int N, int K, float alpha, long sA, long sB, long sC)
{
    extern __shared__ __align__(16) char dsm[];

    A += (long)blockIdx.z * sA;
    B += (long)blockIdx.z * sB;
    C += (long)blockIdx.z * sC;

    const int tid  = threadIdx.x;
    const int wid  = tid >> 5;
    const int lane = tid & 31;
    const int wm   = wid & 1;      // 0..1
    const int wn   = wid >> 1;     // 0..3
    const int bm = blockIdx.y * BM;
    const int bn = blockIdx.x * BN;
    const int KT = K / BKF;

    uint32_t sbase = smem_u32(dsm);

    float acc[4][4][4];
#pragma unroll
    for (int i = 0; i < 4; i++)
#pragma unroll
        for (int j = 0; j < 4; j++)
#pragma unroll
            for (int r = 0; r < 4; r++) acc[i][j][r] = 0.f;

    // prologue: stages 0..2
#pragma unroll
    for (int s = 0; s < NSTG - 1; s++) {
        if (s < KT) load_stage_mma(sbase, s, A, B, bm, bn, s * BKF, K, tid);
        asm volatile("cp.async.commit_group;" ::: "memory");
    }

    const int lr = lane >> 2;   // 0..7
    const int lk = lane & 3;    // 0..3

    for (int kt = 0; kt < KT; kt++) {
        __syncthreads();   // all warps done with stage being overwritten
        if (kt + 3 < KT)
            load_stage_mma(sbase, (kt + 3) & 3, A, B, bm, bn, (kt + 3) * BKF, K, tid);
        asm volatile("cp.async.commit_group;" ::: "memory");
        asm volatile("cp.async.wait_group 3;" ::: "memory");
        __syncthreads();   // stage kt visible to all warps

        const uint32_t* sa = (const uint32_t*)(dsm + (size_t)(kt & 3) * STG_BYTES);
        const uint32_t* sb = sa + BM * BKF;

#pragma unroll
        for (int ks = 0; ks < 2; ks++) {
            int kb = ks * 8;
            uint32_t ah[4][4], al[4][4], bh[4][2], bl[4][2];
#pragma unroll
            for (int mf = 0; mf < 4; mf++) {
                int r0 = wm * 64 + mf * 16 + lr;
                split_tf32(lde(sa, r0,     kb + lk),     ah[mf][0], al[mf][0]);
                split_tf32(lde(sa, r0 + 8, kb + lk),     ah[mf][1], al[mf][1]);
                split_tf32(lde(sa, r0,     kb + lk + 4), ah[mf][2], al[mf][2]);
                split_tf32(lde(sa, r0 + 8, kb + lk + 4), ah[mf][3], al[mf][3]);
            }
#pragma unroll
            for (int nf = 0; nf < 4; nf++) {
                int n0 = wn * 32 + nf * 8 + lr;
                split_tf32(lde(sb, n0, kb + lk),     bh[nf][0], bl[nf][0]);
                split_tf32(lde(sb, n0, kb + lk + 4), bh[nf][1], bl[nf][1]);
            }
#pragma unroll
            for (int mf = 0; mf < 4; mf++)
#pragma unroll
                for (int nf = 0; nf < 4; nf++) {
                    mma1688(acc[mf][nf], al[mf], bh[nf]);   // lo*hi
                    mma1688(acc[mf][nf], ah[mf], bl[nf]);   // hi*lo
                    mma1688(acc[mf][nf], ah[mf], bh[nf]);   // hi*hi (exact)
                }
        }
    }

    // epilogue
#pragma unroll
    for (int mf = 0; mf < 4; mf++) {
        int r0 = bm + wm * 64 + mf * 16 + lr;
#pragma unroll
        for (int nf = 0; nf < 4; nf++) {
            int c0 = bn + wn * 32 + nf * 8 + lk * 2;
#pragma unroll
            for (int h = 0; h < 2; h++) {     // h=0: rows r0, h=1: rows r0+8
                int row = r0 + h * 8;
                float vx = acc[mf][nf][2 * h + 0] * alpha;
                float vy = acc[mf][nf][2 * h + 1] * alpha;
                if (bias) { vx += bias[c0]; vy += bias[c0 + 1]; }
                if (RELU2) {
                    vx = fmaxf(vx, 0.f); vx *= vx;
                    vy = fmaxf(vy, 0.f); vy *= vy;
                }
                *(float2*)(C + (long)row * N + c0) = make_float2(vx, vy);
            }
        }
    }
}

// ---------------------------------------------------------------------------
// RMSNorm
// ---------------------------------------------------------------------------
__global__ void __launch_bounds__(256) rmsnorm_kernel(
    const float* __restrict__ x, const float* __restrict__ w,
    float* __restrict__ out)
{
    long row = blockIdx.x;
    const float* xr = x + row * D_DIM;
    int tid = threadIdx.x;

    float s = 0.f;
#pragma unroll
    for (int d = 0; d < 4; d++) {
        float v = xr[tid + d * 256];
        s += v * v;
    }
#pragma unroll
    for (int o = 16; o > 0; o >>= 1) s += __shfl_xor_sync(0xffffffffu, s, o);

    __shared__ float red[8];
    __shared__ float s_inv;
    if ((tid & 31) == 0) red[tid >> 5] = s;
    __syncthreads();
    if (tid == 0) {
        float t = 0.f;
#pragma unroll
        for (int i = 0; i < 8; i++) t += red[i];
        s_inv = 1.0f / (sqrtf(t / (float)D_DIM) + 1e-8f);
    }
    __syncthreads();
    float inv = s_inv;
#pragma unroll
    for (int d = 0; d < 4; d++) {
        int c = tid + d * 256;
        out[row * D_DIM + c] = w[c] * xr[c] * inv;
    }
}

// ---------------------------------------------------------------------------
// Token-shift mixing
// ---------------------------------------------------------------------------
__global__ void __launch_bounds__(256) mix2_kernel(
    const float* __restrict__ h,
    const float* __restrict__ mA, const float* __restrict__ mB,
    float* __restrict__ oA, float* __restrict__ oB)
{
    long row = blockIdx.x;
    long t = row & (S_LEN - 1);
    long prev = (t == 0) ? row : row - 1;
    int tid = threadIdx.x;
#pragma unroll
    for (int d = 0; d < 4; d++) {
        int c = tid + d * 256;
        float cur = h[row * D_DIM + c];
        float pv  = h[prev * D_DIM + c];
        float a = mA[c], b = mB[c];
        oA[row * D_DIM + c] = cur * a + pv * (1.f - a);
        oB[row * D_DIM + c] = cur * b + pv * (1.f - b);
    }
}

// ---------------------------------------------------------------------------
// SIMT SGEMM (kept only for N=64 projections: sa_q, sa_k — exact fp32)
// ---------------------------------------------------------------------------
__global__ void __launch_bounds__(256) gemm_nt(
    const float* __restrict__ A, const float* __restrict__ B,
    const float* __restrict__ bias, float* __restrict__ C,
    int M, int N, int K)
{
    __shared__ float As[16][132];
    __shared__ float Bs[16][132];

    int bm = blockIdx.y * 128;
    int bn = blockIdx.x * 128;
    int tid = threadIdx.x;
    int tr = tid >> 4;
    int tc = tid & 15;

    float acc[8][8];
#pragma unroll
    for (int i = 0; i < 8; i++)
#pragma unroll
        for (int j = 0; j < 8; j++) acc[i][j] = 0.f;

    int lr = tid >> 2;
    int lc = (tid & 3) * 4;

    for (int k0 = 0; k0 < K; k0 += 16) {
#pragma unroll
        for (int half = 0; half < 2; half++) {
            int row = lr + half * 64;
            float4 a4 = *(const float4*)(A + (long)(bm + row) * K + k0 + lc);
            As[lc + 0][row] = a4.x;
            As[lc + 1][row] = a4.y;
            As[lc + 2][row] = a4.z;
            As[lc + 3][row] = a4.w;
            float4 b4 = make_float4(0.f, 0.f, 0.f, 0.f);
            if (bn + row < N)
                b4 = *(const float4*)(B + (long)(bn + row) * K + k0 + lc);
            Bs[lc + 0][row] = b4.x;
            Bs[lc + 1][row] = b4.y;
            Bs[lc + 2][row] = b4.z;
            Bs[lc + 3][row] = b4.w;
        }
        __syncthreads();
#pragma unroll
        for (int kk = 0; kk < 16; kk++) {
            float a[8], b[8];
            *(float4*)&a[0] = *(const float4*)&As[kk][tr * 8];
            *(float4*)&a[4] = *(const float4*)&As[kk][tr * 8 + 4];
            *(float4*)&b[0] = *(const float4*)&Bs[kk][tc * 8];
            *(float4*)&b[4] = *(const float4*)&Bs[kk][tc * 8 + 4];
#pragma unroll
            for (int i = 0; i < 8; i++)
#pragma unroll
                for (int j = 0; j < 8; j++)
                    acc[i][j] += a[i] * b[j];
        }
        __syncthreads();
    }

#pragma unroll
    for (int i = 0; i < 8; i++) {
        long crow = (long)(bm + tr * 8 + i) * N;
#pragma unroll
        for (int j = 0; j < 8; j++) {
            int col = bn + tc * 8 + j;
            if (col < N) {
                float v = acc[i][j];
                if (bias) v += bias[col];
                C[crow + col] = v;
            }
        }
    }
}

// ---------------------------------------------------------------------------
// Sparse attention: top-32, softmax, attn@V. One block per query row.
// ---------------------------------------------------------------------------
__global__ void __launch_bounds__(256) sparse_attn_kernel(
    const float* __restrict__ scores, const float* __restrict__ V,
    float* __restrict__ out)
{
    __shared__ float sc[S_LEN];
    __shared__ float selV[TOPK];
    __shared__ int   selI[TOPK];
    __shared__ float rv[8];
    __shared__ int   ri[8];
    __shared__ float wsel[TOPK];

    long row = blockIdx.x;
    long b = row >> 12;
    int tid = threadIdx.x;

    const float* srow = scores + row * S_LEN;
    for (int i = tid; i < S_LEN; i += 256) sc[i] = srow[i];
    __syncthreads();

    for (int it = 0; it < TOPK; it++) {
        float bv = NEG_INF;
        int bi = 0x7fffffff;
        for (int i = tid; i < S_LEN; i += 256) {
            float v = sc[i];
            if (v > bv || (v == bv && i < bi)) { bv = v; bi = i; }
        }
#pragma unroll
        for (int o = 16; o > 0; o >>= 1) {
            float ov = __shfl_down_sync(0xffffffffu, bv, o);
            int   oi = __shfl_down_sync(0xffffffffu, bi, o);
            if (ov > bv || (ov == bv && oi < bi)) { bv = ov; bi = oi; }
        }
        if ((tid & 31) == 0) { rv[tid >> 5] = bv; ri[tid >> 5] = bi; }
        __syncthreads();
        if (tid == 0) {
            float fv = rv[0]; int fi = ri[0];
#pragma unroll
            for (int w = 1; w < 8; w++) {
                if (rv[w] > fv || (rv[w] == fv && ri[w] < fi)) { fv = rv[w]; fi = ri[w]; }
            }
            selV[it] = fv; selI[it] = fi;
            sc[fi] = NEG_INF;
        }
        __syncthreads();
    }

    if (tid < TOPK) {
        float m = selV[0];
        float e = expf(selV[tid] - m);
        float s = e;
#pragma unroll
        for (int o = 16; o > 0; o >>= 1) s += __shfl_xor_sync(0xffffffffu, s, o);
        wsel[tid] = e / s;
    }
    __syncthreads();

    float acc[4] = {0.f, 0.f, 0.f, 0.f};
    const float* Vb = V + b * (long)S_LEN * D_DIM;
#pragma unroll 1
    for (int j = 0; j < TOPK; j++) {
        float w = wsel[j];
        const float* vr = Vb + (long)selI[j] * D_DIM;
#pragma unroll
        for (int d = 0; d < 4; d++) acc[d] += w * vr[tid + d * 256];
    }
#pragma unroll
    for (int d = 0; d < 4; d++)
        out[row * D_DIM + tid + d * 256] = acc[d];
}

// ---------------------------------------------------------------------------
// Elementwise kernels
// ---------------------------------------------------------------------------
__device__ __forceinline__ float sigmoidf_(float x) { return 1.f / (1.f + expf(-x)); }

__global__ void ew_gate_add(const float* __restrict__ r, const float* __restrict__ a,
                            const float* __restrict__ v, float* __restrict__ out, long n)
{
    long i = (long)blockIdx.x * blockDim.x + threadIdx.x;
    if (i < n) out[i] = sigmoidf_(r[i]) * (a[i] + v[i]);
}

__global__ void ew_add(const float* __restrict__ a, const float* __restrict__ b,
                       float* __restrict__ out, long n)
{
    long i = (long)blockIdx.x * blockDim.x + threadIdx.x;
    if (i < n) out[i] = a[i] + b[i];
}

__global__ void ew_gate_res(const float* __restrict__ res, const float* __restrict__ r,
                            const float* __restrict__ kv, float* __restrict__ out, long n)
{
    long i = (long)blockIdx.x * blockDim.x + threadIdx.x;
    if (i < n) out[i] = res[i] + sigmoidf_(r[i]) * kv[i];
}

// ---------------------------------------------------------------------------
// Host launchers
// ---------------------------------------------------------------------------
static void launch_tc(const float* A, const float* B, const float* bias, float* C,
                      int M, int N, int K, float alpha, int batch,
                      long sA, long sB, long sC, int relu2)
{
    dim3 grid(N / BN, M / BM, batch);
    if (relu2)
        gemm_mma<1><<<grid, 256, GEMM_DSMEM>>>(A, B, bias, C, M, N, K, alpha, sA, sB, sC);
    else
        gemm_mma<0><<<grid, 256, GEMM_DSMEM>>>(A, B, bias, C, M, N, K, alpha, sA, sB, sC);
}

extern "C" void kernel_launch(void* const* d_in, const int* in_sizes, int n_in,
                              void* d_out, int out_size)
{
    const float* x         = (const float*)d_in[0];
    const float* norm1_w   = (const float*)d_in[1];
    const float* tm_mix_v  = (const float*)d_in[3];
    const float* tm_mix_r  = (const float*)d_in[4];
    const float* tm_value_w  = (const float*)d_in[6];
    const float* tm_recept_w = (const float*)d_in[7];
    const float* tm_out_w    = (const float*)d_in[8];
    const float* sa_q_w    = (const float*)d_in[9];
    const float* sa_q_b    = (const float*)d_in[10];
    const float* sa_k_w    = (const float*)d_in[11];
    const float* sa_k_b    = (const float*)d_in[12];
    const float* sa_v_w    = (const float*)d_in[13];
    const float* sa_v_b    = (const float*)d_in[14];
    const float* sa_o_w    = (const float*)d_in[15];
    const float* sa_o_b    = (const float*)d_in[16];
    const float* norm2_w   = (const float*)d_in[17];
    const float* cm_mix_k  = (const float*)d_in[18];
    const float* cm_mix_r  = (const float*)d_in[19];
    const float* cm_key_w    = (const float*)d_in[20];
    const float* cm_recept_w = (const float*)d_in[21];
    const float* cm_value_w  = (const float*)d_in[22];
    float* out = (float*)d_out;

    cudaFuncSetAttribute(gemm_mma<0>, cudaFuncAttributeMaxDynamicSharedMemorySize, GEMM_DSMEM);
    cudaFuncSetAttribute(gemm_mma<1>, cudaFuncAttributeMaxDynamicSharedMemorySize, GEMM_DSMEM);

    float* sp = nullptr;
    cudaGetSymbolAddress((void**)&sp, g_scratch);

    float* h1    = sp + O_H1;
    float* xv    = sp + O_XV;
    float* xr    = sp + O_XR;
    float* Vtm   = sp + O_VTM;
    float* Rtm   = sp + O_RTM;
    float* Vv    = sp + O_VV;
    float* attn  = sp + O_ATTN;
    float* attno = sp + O_ATTNO;
    float* x2    = sp + O_X2;
    float* R2    = sp + O_R2;
    float* KV    = sp + O_KV;
    float* Q     = sp + O_Q;
    float* Kk    = sp + O_KK;
    float* SCo   = sp + O_SC;
    float* Kc    = sp + O_KC;

    const long n = ROWELEMS;
    const int ewBlocks = (int)((n + 255) / 256);

    // --- time-mix branch ---
    rmsnorm_kernel<<<NROWS, 256>>>(x, norm1_w, h1);
    mix2_kernel<<<NROWS, 256>>>(h1, tm_mix_v, tm_mix_r, xv, xr);

    launch_tc(xv, tm_value_w,  nullptr, Vtm, NROWS, D_DIM, D_DIM, 1.f, 1, 0, 0, 0, 0);
    launch_tc(xr, tm_recept_w, nullptr, Rtm, NROWS, D_DIM, D_DIM, 1.f, 1, 0, 0, 0, 0);

    // small N=64 projections on SIMT path (fp32 keeps scores input exact)
    {
        dim3 g1(1, NROWS / 128, 1);
        gemm_nt<<<g1, 256>>>(h1, sa_q_w, sa_q_b, Q,  NROWS, A_DIM, D_DIM);
        gemm_nt<<<g1, 256>>>(h1, sa_k_w, sa_k_b, Kk, NROWS, A_DIM, D_DIM);
    }

    launch_tc(h1, sa_v_w, sa_v_b, Vv, NROWS, D_DIM, D_DIM, 1.f, 1, 0, 0, 0, 0);

    // scores[b] = (Q[b] @ K[b]^T) / sqrt(A)
    launch_tc(Q, Kk, nullptr, SCo, S_LEN, S_LEN, A_DIM, 0.125f, B_SZ,
              (long)S_LEN * A_DIM, (long)S_LEN * A_DIM, (long)S_LEN * S_LEN, 0);

    sparse_attn_kernel<<<NROWS, 256>>>(SCo, Vv, attn);

    launch_tc(attn, sa_o_w, sa_o_b, attno, NROWS, D_DIM, D_DIM, 1.f, 1, 0, 0, 0, 0);

    ew_gate_add<<<ewBlocks, 256>>>(Rtm, attno, Vtm, attn, n);

    launch_tc(attn, tm_out_w, nullptr, Vtm, NROWS, D_DIM, D_DIM, 1.f, 1, 0, 0, 0, 0);
    ew_add<<<ewBlocks, 256>>>(x, Vtm, x2, n);

    // --- channel-mix branch ---
    rmsnorm_kernel<<<NROWS, 256>>>(x2, norm2_w, h1);
    mix2_kernel<<<NROWS, 256>>>(h1, cm_mix_k, cm_mix_r, xv, xr);

    launch_tc(xv, cm_key_w, nullptr, Kc, NROWS, DI_DIM, D_DIM, 1.f, 1, 0, 0, 0, 1);
    launch_tc(xr, cm_recept_w, nullptr, R2, NROWS, D_DIM, D_DIM, 1.f, 1, 0, 0, 0, 0);
    launch_tc(Kc, cm_value_w, nullptr, KV, NROWS, D_DIM, DI_DIM, 1.f, 1, 0, 0, 0, 0);

    ew_gate_res<<<ewBlocks, 256>>>(x2, R2, KV, out, n);
}